// round 14
// baseline (speedup 1.0000x reference)
#include <cuda_runtime.h>
#include <math.h>

// Problem constants
#define Bq  4
#define Lq  2048
#define Dq  1024
#define Hq  16
#define HDq 64

typedef unsigned long long u64;

// Scratch (allocation-free rule: __device__ globals)
__device__ float g_q [(size_t)Bq * Lq * Dq];
__device__ float g_k [(size_t)Bq * Lq * Dq];
__device__ float g_v [(size_t)Bq * Lq * Dq];
__device__ float g_oh[(size_t)Bq * Lq * Dq];
// Fallback attention scratch in case d_out only holds `out`
__device__ float g_attn[(size_t)Bq * Hq * Lq * Lq];

// ---------------------------------------------------------------------------
// Packed f32x2 helpers
// ---------------------------------------------------------------------------
__device__ __forceinline__ void fma2(u64& d, u64 a, u64 b) {
    asm("fma.rn.f32x2 %0, %1, %2, %0;" : "+l"(d) : "l"(a), "l"(b));
}
__device__ __forceinline__ void mul2(u64& d, u64 a, u64 b) {
    asm("mul.rn.f32x2 %0, %1, %2;" : "=l"(d) : "l"(a), "l"(b));
}
__device__ __forceinline__ void add2(u64& d, u64 a, u64 b) {
    asm("add.rn.f32x2 %0, %1, %2;" : "=l"(d) : "l"(a), "l"(b));
}
__device__ __forceinline__ u64 dup2(float x) {
    u64 r;
    asm("mov.b64 %0, {%1, %1};" : "=l"(r) : "f"(x));
    return r;
}

// ---------------------------------------------------------------------------
// NT GEMM: C[m,n] = alpha * sum_k A[m,k]*B[n,k] (+bias[n])
// 128x128 tile, BK=8, 256 threads, 8x8 outputs as packed f32x2 accumulators.
// Double-buffered smem + register prefetch. Batched over blockIdx.z.
// ---------------------------------------------------------------------------
__global__ __launch_bounds__(256)
void gemm_nt(const float* __restrict__ A, const float* __restrict__ B,
             float* __restrict__ C,
             int K, int lda, int ldb, int ldc,
             long long sA1, long long sA2,
             long long sB1, long long sB2,
             long long sC1, long long sC2, int Hdiv,
             float alpha, const float* __restrict__ bias)
{
    int z  = blockIdx.z;
    int bq = z / Hdiv, hq = z % Hdiv;
    A += (long long)bq * sA1 + (long long)hq * sA2;
    B += (long long)bq * sB1 + (long long)hq * sB2;
    C += (long long)bq * sC1 + (long long)hq * sC2;

    const int bm = blockIdx.y * 128;
    const int bn = blockIdx.x * 128;

    __shared__ float As[2][8][128];
    __shared__ float Bs[2][8][128];

    const int tid = threadIdx.x;
    const int tx  = tid & 15;
    const int ty  = tid >> 4;
    const int lr  = tid >> 1;
    const int lk  = (tid & 1) << 2;

    const float* Ap = A + (long long)(bm + lr) * lda + lk;
    const float* Bp = B + (long long)(bn + lr) * ldb + lk;

    u64 acc[8][4];
#pragma unroll
    for (int i = 0; i < 8; i++)
#pragma unroll
        for (int j = 0; j < 4; j++) acc[i][j] = 0ull;

    float4 a4 = *(const float4*)(Ap);
    float4 b4 = *(const float4*)(Bp);
    As[0][lk + 0][lr] = a4.x; As[0][lk + 1][lr] = a4.y;
    As[0][lk + 2][lr] = a4.z; As[0][lk + 3][lr] = a4.w;
    Bs[0][lk + 0][lr] = b4.x; Bs[0][lk + 1][lr] = b4.y;
    Bs[0][lk + 2][lr] = b4.z; Bs[0][lk + 3][lr] = b4.w;
    __syncthreads();

    int p = 0;
    for (int k0 = 0; k0 < K; k0 += 8) {
        const bool nxt = (k0 + 8) < K;
        if (nxt) {
            a4 = *(const float4*)(Ap + k0 + 8);
            b4 = *(const float4*)(Bp + k0 + 8);
        }
#pragma unroll
        for (int kk = 0; kk < 8; kk++) {
            float ar[8];
            *(float4*)(ar)     = *(const float4*)(&As[p][kk][ty * 4]);
            *(float4*)(ar + 4) = *(const float4*)(&As[p][kk][ty * 4 + 64]);
            ulonglong2 bl0 = *(const ulonglong2*)(&Bs[p][kk][tx * 4]);
            ulonglong2 bl1 = *(const ulonglong2*)(&Bs[p][kk][tx * 4 + 64]);
            u64 bb[4] = { bl0.x, bl0.y, bl1.x, bl1.y };
#pragma unroll
            for (int i = 0; i < 8; i++) {
                u64 ad = dup2(ar[i]);
#pragma unroll
                for (int j = 0; j < 4; j++) fma2(acc[i][j], ad, bb[j]);
            }
        }
        if (nxt) {
            p ^= 1;
            As[p][lk + 0][lr] = a4.x; As[p][lk + 1][lr] = a4.y;
            As[p][lk + 2][lr] = a4.z; As[p][lk + 3][lr] = a4.w;
            Bs[p][lk + 0][lr] = b4.x; Bs[p][lk + 1][lr] = b4.y;
            Bs[p][lk + 2][lr] = b4.z; Bs[p][lk + 3][lr] = b4.w;
            __syncthreads();
        }
    }

    u64 alpha2 = dup2(alpha);
#pragma unroll
    for (int ih = 0; ih < 2; ih++) {
#pragma unroll
        for (int i = 0; i < 4; i++) {
            int r = bm + ty * 4 + i + ih * 64;
#pragma unroll
            for (int jh = 0; jh < 2; jh++) {
                int c = bn + tx * 4 + jh * 64;
                u64 v0 = acc[ih * 4 + i][jh * 2 + 0];
                u64 v1 = acc[ih * 4 + i][jh * 2 + 1];
                mul2(v0, v0, alpha2);
                mul2(v1, v1, alpha2);
                if (bias) {
                    ulonglong2 bb = *(const ulonglong2*)(&bias[c]);
                    add2(v0, v0, bb.x);
                    add2(v1, v1, bb.y);
                }
                ulonglong2 ov; ov.x = v0; ov.y = v1;
                *(ulonglong2*)(C + (long long)r * ldc + c) = ov;
            }
        }
    }
}

// ---------------------------------------------------------------------------
// Fused softmax + AV.
// Block = 128 rows of one (b,h) head. 256 threads.
// Phase 1: row maxes over the 2048-wide energy rows.
// Phase 2: per 32-col chunk: p = exp(e - max); write p (unnormalized) to attn;
//          stage P-chunk (k-major) + V-chunk in smem; accumulate O += P@V.
// Phase 3: rowsum -> 1/s; scale O and write out_head; rescale attn in place.
// ---------------------------------------------------------------------------
__global__ __launch_bounds__(256)
void fused_sm_av(float* __restrict__ E,        // attn buffer [B*H][L][L]
                 const float* __restrict__ V,  // [B][L][D]
                 float* __restrict__ C)        // out_head [B][L][D]
{
    const int z  = blockIdx.y;
    const int bq = z / Hq, hq = z % Hq;
    const int bm = blockIdx.x * 128;

    float* Eb = E + (long long)z * Lq * Lq + (long long)bm * Lq;
    const float* Vb = V + (long long)bq * Lq * Dq + hq * HDq;
    float*       Cb = C + (long long)bq * Lq * Dq + hq * HDq;

    __shared__ float Ps[32][132];     // [kk][m], padded stride
    __shared__ float Vs[32][64];      // [kk][n]
    __shared__ float halfred[256];
    __shared__ float rowmax[128];
    __shared__ float rowsuminv[128];

    const int tid = threadIdx.x;
    const int row = tid >> 1;         // 0..127 (E row handled by this thread)
    const int sub = tid & 1;          // which interleaved half of the row
    const int tx  = tid & 15;         // AV: output col group (4 cols)
    const int ty  = tid >> 4;         // AV: output row group

    float* erow = Eb + (long long)row * Lq;

    // ---- Phase 1: row max ----
    float m = -3.402823466e+38f;
#pragma unroll 4
    for (int jj = 0; jj < 256; jj++) {
        float4 x = *(const float4*)(erow + sub * 4 + 8 * jj);
        m = fmaxf(m, fmaxf(fmaxf(x.x, x.y), fmaxf(x.z, x.w)));
    }
    halfred[tid] = m;
    __syncthreads();
    if (tid < 128)
        rowmax[tid] = fmaxf(halfred[2 * tid], halfred[2 * tid + 1]);
    __syncthreads();
    const float rmax = rowmax[row];

    // ---- Phase 2: exp + write unnormalized + AV accumulate ----
    const int vrow = tid >> 3;            // 0..31 (V chunk row)
    const int vc   = (tid & 7) * 4;       // V col base (float4 granularity)

    u64 acc[8][2];
#pragma unroll
    for (int i = 0; i < 8; i++) { acc[i][0] = 0ull; acc[i][1] = 0ull; }

    float psum = 0.f;

    for (int k0 = 0; k0 < Lq; k0 += 32) {
        // load E chunk (4 float4 per thread) + V chunk (2 float4 per thread)
        float4 ex[4];
#pragma unroll
        for (int jj = 0; jj < 4; jj++)
            ex[jj] = *(const float4*)(erow + k0 + sub * 4 + 8 * jj);
        float4 vv0 = *(const float4*)(Vb + (long long)(k0 + vrow) * Dq + vc);
        float4 vv1 = *(const float4*)(Vb + (long long)(k0 + vrow) * Dq + vc + 32);

        // exp
#pragma unroll
        for (int jj = 0; jj < 4; jj++) {
            ex[jj].x = expf(ex[jj].x - rmax);
            ex[jj].y = expf(ex[jj].y - rmax);
            ex[jj].z = expf(ex[jj].z - rmax);
            ex[jj].w = expf(ex[jj].w - rmax);
            psum += ex[jj].x + ex[jj].y + ex[jj].z + ex[jj].w;
        }

        __syncthreads();   // previous chunk's AV reads done

        // stage P (k-major) and V; write unnormalized p to global
#pragma unroll
        for (int jj = 0; jj < 4; jj++) {
            int kk = sub * 4 + 8 * jj;
            Ps[kk + 0][row] = ex[jj].x;
            Ps[kk + 1][row] = ex[jj].y;
            Ps[kk + 2][row] = ex[jj].z;
            Ps[kk + 3][row] = ex[jj].w;
            *(float4*)(erow + k0 + kk) = ex[jj];
        }
        *(float4*)(&Vs[vrow][vc])      = vv0;
        *(float4*)(&Vs[vrow][vc + 32]) = vv1;

        __syncthreads();

        // AV micro-GEMM: O[128x64] += P[128x32] @ V[32x64]
#pragma unroll
        for (int kk = 0; kk < 32; kk++) {
            float ar[8];
            *(float4*)(ar)     = *(const float4*)(&Ps[kk][ty * 4]);
            *(float4*)(ar + 4) = *(const float4*)(&Ps[kk][ty * 4 + 64]);
            ulonglong2 bb = *(const ulonglong2*)(&Vs[kk][tx * 4]);
#pragma unroll
            for (int i = 0; i < 8; i++) {
                u64 ad = dup2(ar[i]);
                fma2(acc[i][0], ad, bb.x);
                fma2(acc[i][1], ad, bb.y);
            }
        }
    }

    // ---- Phase 3: sums, scale O, normalize attn ----
    __syncthreads();
    halfred[tid] = psum;
    __syncthreads();
    if (tid < 128)
        rowsuminv[tid] = 1.0f / (halfred[2 * tid] + halfred[2 * tid + 1]);
    __syncthreads();

    // scale O and write out_head
#pragma unroll
    for (int ih = 0; ih < 2; ih++) {
#pragma unroll
        for (int i = 0; i < 4; i++) {
            int r = ty * 4 + i + ih * 64;
            u64 inv2 = dup2(rowsuminv[r]);
            u64 v0 = acc[ih * 4 + i][0];
            u64 v1 = acc[ih * 4 + i][1];
            mul2(v0, v0, inv2);
            mul2(v1, v1, inv2);
            ulonglong2 ov; ov.x = v0; ov.y = v1;
            *(ulonglong2*)(&Cb[(long long)(bm + r) * Dq + tx * 4]) = ov;
        }
    }

    // normalize attention rows in place (re-read own writes; L2/L1 hot)
    const float rinv = rowsuminv[row];
#pragma unroll 4
    for (int jj = 0; jj < 256; jj++) {
        float* ptr = erow + sub * 4 + 8 * jj;
        float4 x = *(const float4*)(ptr);
        x.x *= rinv; x.y *= rinv; x.z *= rinv; x.w *= rinv;
        *(float4*)(ptr) = x;
    }
}

// ---------------------------------------------------------------------------
// Launch
// ---------------------------------------------------------------------------
extern "C" void kernel_launch(void* const* d_in, const int* in_sizes, int n_in,
                              void* d_out, int out_size)
{
    const float* query = (const float*)d_in[0];
    const float* key   = (const float*)d_in[1];
    const float* value = (const float*)d_in[2];
    const float* Wq    = (const float*)d_in[3];
    const float* Wk    = (const float*)d_in[4];
    const float* Wv    = (const float*)d_in[5];
    const float* Wo    = (const float*)d_in[6];
    const float* bo    = (const float*)d_in[7];

    float* out = (float*)d_out;

    const long long BLD  = (long long)Bq * Lq * Dq;
    const long long BHLL = (long long)Bq * Hq * Lq * Lq;

    float *pq, *pk, *pv, *poh, *pattn_scratch;
    cudaGetSymbolAddress((void**)&pq,  g_q);
    cudaGetSymbolAddress((void**)&pk,  g_k);
    cudaGetSymbolAddress((void**)&pv,  g_v);
    cudaGetSymbolAddress((void**)&poh, g_oh);
    cudaGetSymbolAddress((void**)&pattn_scratch, g_attn);

    float* attn = ((long long)out_size >= BLD + BHLL) ? (out + BLD)
                                                      : pattn_scratch;

    dim3 blk(256);

    // 1) QKV projections
    {
        dim3 grd(Dq / 128, (Bq * Lq) / 128, 1);
        gemm_nt<<<grd, blk>>>(query, Wq, pq, Dq, Dq, Dq, Dq,
                              0, 0, 0, 0, 0, 0, 1, 1.0f, (const float*)0);
        gemm_nt<<<grd, blk>>>(key,   Wk, pk, Dq, Dq, Dq, Dq,
                              0, 0, 0, 0, 0, 0, 1, 1.0f, (const float*)0);
        gemm_nt<<<grd, blk>>>(value, Wv, pv, Dq, Dq, Dq, Dq,
                              0, 0, 0, 0, 0, 0, 1, 1.0f, (const float*)0);
    }

    // 2) Scores: per (b,h): S = (1/8) * Q_bh @ K_bh^T
    {
        dim3 grd(Lq / 128, Lq / 128, Bq * Hq);
        gemm_nt<<<grd, blk>>>(pq, pk, attn, HDq, Dq, Dq, Lq,
                              (long long)Lq * Dq, (long long)HDq,
                              (long long)Lq * Dq, (long long)HDq,
                              (long long)Hq * Lq * Lq, (long long)Lq * Lq,
                              Hq, 0.125f, (const float*)0);
    }

    // 3+4) Fused softmax + AV
    {
        dim3 grd(Lq / 128, Bq * Hq);
        fused_sm_av<<<grd, blk>>>(attn, pv, poh);
    }

    // 5) Output projection: out = out_head @ Wo^T + bo
    {
        dim3 grd(Dq / 128, (Bq * Lq) / 128, 1);
        gemm_nt<<<grd, blk>>>(poh, Wo, out, Dq, Dq, Dq, Dq,
                              0, 0, 0, 0, 0, 0, 1, 1.0f, bo);
    }
}

// round 15
// speedup vs baseline: 1.0640x; 1.0640x over previous
#include <cuda_runtime.h>
#include <math.h>

// Problem constants
#define Bq  4
#define Lq  2048
#define Dq  1024
#define Hq  16
#define HDq 64

typedef unsigned long long u64;

// Scratch (allocation-free rule: __device__ globals)
__device__ float g_q [(size_t)Bq * Lq * Dq];
__device__ float g_k [(size_t)Bq * Lq * Dq];
__device__ float g_v [(size_t)Bq * Lq * Dq];
__device__ float g_oh[(size_t)Bq * Lq * Dq];
__device__ float g_rmax[(size_t)Bq * Hq * Lq];
__device__ float g_rinv[(size_t)Bq * Hq * Lq];
// Fallback attention scratch in case d_out only holds `out`
__device__ float g_attn[(size_t)Bq * Hq * Lq * Lq];

// ---------------------------------------------------------------------------
// Packed f32x2 helpers
// ---------------------------------------------------------------------------
__device__ __forceinline__ void fma2(u64& d, u64 a, u64 b) {
    asm("fma.rn.f32x2 %0, %1, %2, %0;" : "+l"(d) : "l"(a), "l"(b));
}
__device__ __forceinline__ void mul2(u64& d, u64 a, u64 b) {
    asm("mul.rn.f32x2 %0, %1, %2;" : "=l"(d) : "l"(a), "l"(b));
}
__device__ __forceinline__ void add2(u64& d, u64 a, u64 b) {
    asm("add.rn.f32x2 %0, %1, %2;" : "=l"(d) : "l"(a), "l"(b));
}
__device__ __forceinline__ u64 dup2(float x) {
    u64 r;
    asm("mov.b64 %0, {%1, %1};" : "=l"(r) : "f"(x));
    return r;
}

// ---------------------------------------------------------------------------
// NT GEMM: C[m,n] = alpha * sum_k A[m,k]*B[n,k] (+bias[n])
// 128x128 tile, BK=16, 256 threads, 8x8 outputs as packed f32x2 accumulators.
// Double-buffered smem (1 sync per 16 k) + register prefetch.
// ---------------------------------------------------------------------------
__global__ __launch_bounds__(256, 2)
void gemm_nt(const float* __restrict__ A, const float* __restrict__ B,
             float* __restrict__ C,
             int K, int lda, int ldb, int ldc,
             long long sA1, long long sA2,
             long long sB1, long long sB2,
             long long sC1, long long sC2, int Hdiv,
             float alpha, const float* __restrict__ bias)
{
    int z  = blockIdx.z;
    int bq = z / Hdiv, hq = z % Hdiv;
    A += (long long)bq * sA1 + (long long)hq * sA2;
    B += (long long)bq * sB1 + (long long)hq * sB2;
    C += (long long)bq * sC1 + (long long)hq * sC2;

    const int bm = blockIdx.y * 128;
    const int bn = blockIdx.x * 128;

    __shared__ float As[2][16][128];
    __shared__ float Bs[2][16][128];

    const int tid = threadIdx.x;
    const int tx  = tid & 15;
    const int ty  = tid >> 4;
    const int lr  = tid >> 1;
    const int lk  = (tid & 1) << 2;   // covers k = lk..lk+3 and lk+8..lk+11

    const float* Ap = A + (long long)(bm + lr) * lda + lk;
    const float* Bp = B + (long long)(bn + lr) * ldb + lk;

    u64 acc[8][4];
#pragma unroll
    for (int i = 0; i < 8; i++)
#pragma unroll
        for (int j = 0; j < 4; j++) acc[i][j] = 0ull;

    // Prologue: fill buffer 0
    float4 aA = *(const float4*)(Ap);
    float4 aB = *(const float4*)(Ap + 8);
    float4 bA = *(const float4*)(Bp);
    float4 bB = *(const float4*)(Bp + 8);
    As[0][lk + 0][lr] = aA.x; As[0][lk + 1][lr] = aA.y;
    As[0][lk + 2][lr] = aA.z; As[0][lk + 3][lr] = aA.w;
    As[0][lk + 8][lr] = aB.x; As[0][lk + 9][lr] = aB.y;
    As[0][lk +10][lr] = aB.z; As[0][lk +11][lr] = aB.w;
    Bs[0][lk + 0][lr] = bA.x; Bs[0][lk + 1][lr] = bA.y;
    Bs[0][lk + 2][lr] = bA.z; Bs[0][lk + 3][lr] = bA.w;
    Bs[0][lk + 8][lr] = bB.x; Bs[0][lk + 9][lr] = bB.y;
    Bs[0][lk +10][lr] = bB.z; Bs[0][lk +11][lr] = bB.w;
    __syncthreads();

    int p = 0;
    for (int k0 = 0; k0 < K; k0 += 16) {
        const bool nxt = (k0 + 16) < K;
        if (nxt) {
            aA = *(const float4*)(Ap + k0 + 16);
            aB = *(const float4*)(Ap + k0 + 24);
            bA = *(const float4*)(Bp + k0 + 16);
            bB = *(const float4*)(Bp + k0 + 24);
        }
#pragma unroll
        for (int kk = 0; kk < 16; kk++) {
            float ar[8];
            *(float4*)(ar)     = *(const float4*)(&As[p][kk][ty * 4]);
            *(float4*)(ar + 4) = *(const float4*)(&As[p][kk][ty * 4 + 64]);
            ulonglong2 bl0 = *(const ulonglong2*)(&Bs[p][kk][tx * 4]);
            ulonglong2 bl1 = *(const ulonglong2*)(&Bs[p][kk][tx * 4 + 64]);
            u64 bb[4] = { bl0.x, bl0.y, bl1.x, bl1.y };
#pragma unroll
            for (int i = 0; i < 8; i++) {
                u64 ad = dup2(ar[i]);
#pragma unroll
                for (int j = 0; j < 4; j++) fma2(acc[i][j], ad, bb[j]);
            }
        }
        if (nxt) {
            p ^= 1;
            As[p][lk + 0][lr] = aA.x; As[p][lk + 1][lr] = aA.y;
            As[p][lk + 2][lr] = aA.z; As[p][lk + 3][lr] = aA.w;
            As[p][lk + 8][lr] = aB.x; As[p][lk + 9][lr] = aB.y;
            As[p][lk +10][lr] = aB.z; As[p][lk +11][lr] = aB.w;
            Bs[p][lk + 0][lr] = bA.x; Bs[p][lk + 1][lr] = bA.y;
            Bs[p][lk + 2][lr] = bA.z; Bs[p][lk + 3][lr] = bA.w;
            Bs[p][lk + 8][lr] = bB.x; Bs[p][lk + 9][lr] = bB.y;
            Bs[p][lk +10][lr] = bB.z; Bs[p][lk +11][lr] = bB.w;
            __syncthreads();
        }
    }

    u64 alpha2 = dup2(alpha);
#pragma unroll
    for (int ih = 0; ih < 2; ih++) {
#pragma unroll
        for (int i = 0; i < 4; i++) {
            int r = bm + ty * 4 + i + ih * 64;
#pragma unroll
            for (int jh = 0; jh < 2; jh++) {
                int c = bn + tx * 4 + jh * 64;
                u64 v0 = acc[ih * 4 + i][jh * 2 + 0];
                u64 v1 = acc[ih * 4 + i][jh * 2 + 1];
                mul2(v0, v0, alpha2);
                mul2(v1, v1, alpha2);
                if (bias) {
                    ulonglong2 bb = *(const ulonglong2*)(&bias[c]);
                    add2(v0, v0, bb.x);
                    add2(v1, v1, bb.y);
                }
                ulonglong2 ov; ov.x = v0; ov.y = v1;
                *(ulonglong2*)(C + (long long)r * ldc + c) = ov;
            }
        }
    }
}

// ---------------------------------------------------------------------------
// Softmax stats: one warp per 2048-wide row. Produces rowmax and 1/sum(exp).
// Row kept register-resident (single global read of E).
// ---------------------------------------------------------------------------
__global__ __launch_bounds__(256)
void softmax_stats(const float* __restrict__ E,
                   float* __restrict__ rmax, float* __restrict__ rinv)
{
    const int warp = threadIdx.x >> 5;
    const int lane = threadIdx.x & 31;
    const long long row = (long long)blockIdx.x * 8 + warp;

    const float* p = E + row * Lq + lane * 4;

    float4 v[16];
#pragma unroll
    for (int i = 0; i < 16; i++) v[i] = *(const float4*)(p + i * 128);

    float m = -3.402823466e+38f;
#pragma unroll
    for (int i = 0; i < 16; i++)
        m = fmaxf(m, fmaxf(fmaxf(v[i].x, v[i].y), fmaxf(v[i].z, v[i].w)));
#pragma unroll
    for (int o = 16; o; o >>= 1) m = fmaxf(m, __shfl_xor_sync(0xffffffffu, m, o));

    float s = 0.f;
#pragma unroll
    for (int i = 0; i < 16; i++) {
        s += expf(v[i].x - m) + expf(v[i].y - m)
           + expf(v[i].z - m) + expf(v[i].w - m);
    }
#pragma unroll
    for (int o = 16; o; o >>= 1) s += __shfl_xor_sync(0xffffffffu, s, o);

    if (lane == 0) {
        rmax[row] = m;
        rinv[row] = 1.0f / s;
    }
}

// ---------------------------------------------------------------------------
// Fused normalize + AV: per (b,h) head, 128-row tile, 128 threads.
// A-chunk sourced from energies: p = expf(e - rowmax) * rowinv, written back
// to the attention buffer in place AND staged in smem for the AV micro-GEMM.
// O[128x64] += P[128x2048] @ V[2048x64], fully normalized on the fly.
// ---------------------------------------------------------------------------
__global__ __launch_bounds__(128)
void av_norm(float* __restrict__ E,           // energies in, probs out
             const float* __restrict__ V,
             float* __restrict__ C,
             const float* __restrict__ rmax,
             const float* __restrict__ rinv)
{
    int z  = blockIdx.z;
    int bq = z / Hq, hq = z % Hq;
    float*       Ab = E + (long long)z * Lq * Lq;
    const float* Bb = V + (long long)bq * Lq * Dq + hq * HDq;
    float*       Cb = C + (long long)bq * Lq * Dq + hq * HDq;

    const int bm = blockIdx.x * 128;

    __shared__ float As[2][8][128];
    __shared__ float Bs[2][8][64];

    const int tid = threadIdx.x;
    const int tx  = tid & 7;
    const int ty  = tid >> 3;

    float* Ap = Ab + (long long)(bm + tid) * Lq;
    const int bvr = tid >> 4;
    const int bvc = (tid & 15) * 4;
    const float* Bp = Bb + (long long)bvr * Dq + bvc;

    const float em  = rmax[(long long)z * Lq + bm + tid];
    const float inv = rinv[(long long)z * Lq + bm + tid];

    u64 acc[8][4];
#pragma unroll
    for (int i = 0; i < 8; i++)
#pragma unroll
        for (int j = 0; j < 4; j++) acc[i][j] = 0ull;

    // Prologue: load, transform, stage + write back chunk 0
    float4 a0 = *(const float4*)(Ap);
    float4 a1 = *(const float4*)(Ap + 4);
    float4 b0 = *(const float4*)(Bp);
    a0.x = expf(a0.x - em) * inv; a0.y = expf(a0.y - em) * inv;
    a0.z = expf(a0.z - em) * inv; a0.w = expf(a0.w - em) * inv;
    a1.x = expf(a1.x - em) * inv; a1.y = expf(a1.y - em) * inv;
    a1.z = expf(a1.z - em) * inv; a1.w = expf(a1.w - em) * inv;
    As[0][0][tid] = a0.x; As[0][1][tid] = a0.y;
    As[0][2][tid] = a0.z; As[0][3][tid] = a0.w;
    As[0][4][tid] = a1.x; As[0][5][tid] = a1.y;
    As[0][6][tid] = a1.z; As[0][7][tid] = a1.w;
    *(float4*)(Ap)     = a0;
    *(float4*)(Ap + 4) = a1;
    *(float4*)(&Bs[0][bvr][bvc]) = b0;
    __syncthreads();

    int p = 0;
    for (int k0 = 0; k0 < Lq; k0 += 8) {
        const bool nxt = (k0 + 8) < Lq;
        if (nxt) {
            a0 = *(const float4*)(Ap + k0 + 8);
            a1 = *(const float4*)(Ap + k0 + 12);
            b0 = *(const float4*)(Bp + (long long)(k0 + 8) * Dq);
        }
#pragma unroll
        for (int kk = 0; kk < 8; kk++) {
            float ar[8];
            *(float4*)(ar)     = *(const float4*)(&As[p][kk][ty * 4]);
            *(float4*)(ar + 4) = *(const float4*)(&As[p][kk][ty * 4 + 64]);
            ulonglong2 bl0 = *(const ulonglong2*)(&Bs[p][kk][tx * 4]);
            ulonglong2 bl1 = *(const ulonglong2*)(&Bs[p][kk][tx * 4 + 32]);
            u64 bb[4] = { bl0.x, bl0.y, bl1.x, bl1.y };
#pragma unroll
            for (int i = 0; i < 8; i++) {
                u64 ad = dup2(ar[i]);
#pragma unroll
                for (int j = 0; j < 4; j++) fma2(acc[i][j], ad, bb[j]);
            }
        }
        if (nxt) {
            a0.x = expf(a0.x - em) * inv; a0.y = expf(a0.y - em) * inv;
            a0.z = expf(a0.z - em) * inv; a0.w = expf(a0.w - em) * inv;
            a1.x = expf(a1.x - em) * inv; a1.y = expf(a1.y - em) * inv;
            a1.z = expf(a1.z - em) * inv; a1.w = expf(a1.w - em) * inv;
            p ^= 1;
            As[p][0][tid] = a0.x; As[p][1][tid] = a0.y;
            As[p][2][tid] = a0.z; As[p][3][tid] = a0.w;
            As[p][4][tid] = a1.x; As[p][5][tid] = a1.y;
            As[p][6][tid] = a1.z; As[p][7][tid] = a1.w;
            *(float4*)(Ap + k0 + 8)  = a0;
            *(float4*)(Ap + k0 + 12) = a1;
            *(float4*)(&Bs[p][bvr][bvc]) = b0;
            __syncthreads();
        }
    }

#pragma unroll
    for (int ih = 0; ih < 2; ih++) {
#pragma unroll
        for (int i = 0; i < 4; i++) {
            int r = bm + ih * 64 + ty * 4 + i;
            ulonglong2 ov0, ov1;
            ov0.x = acc[ih * 4 + i][0]; ov0.y = acc[ih * 4 + i][1];
            ov1.x = acc[ih * 4 + i][2]; ov1.y = acc[ih * 4 + i][3];
            *(ulonglong2*)(&Cb[(long long)r * Dq + tx * 4])      = ov0;
            *(ulonglong2*)(&Cb[(long long)r * Dq + 32 + tx * 4]) = ov1;
        }
    }
}

// ---------------------------------------------------------------------------
// Launch
// ---------------------------------------------------------------------------
extern "C" void kernel_launch(void* const* d_in, const int* in_sizes, int n_in,
                              void* d_out, int out_size)
{
    const float* query = (const float*)d_in[0];
    const float* key   = (const float*)d_in[1];
    const float* value = (const float*)d_in[2];
    const float* Wq    = (const float*)d_in[3];
    const float* Wk    = (const float*)d_in[4];
    const float* Wv    = (const float*)d_in[5];
    const float* Wo    = (const float*)d_in[6];
    const float* bo    = (const float*)d_in[7];

    float* out = (float*)d_out;

    const long long BLD  = (long long)Bq * Lq * Dq;
    const long long BHLL = (long long)Bq * Hq * Lq * Lq;

    float *pq, *pk, *pv, *poh, *pattn_scratch, *prmax, *prinv;
    cudaGetSymbolAddress((void**)&pq,  g_q);
    cudaGetSymbolAddress((void**)&pk,  g_k);
    cudaGetSymbolAddress((void**)&pv,  g_v);
    cudaGetSymbolAddress((void**)&poh, g_oh);
    cudaGetSymbolAddress((void**)&pattn_scratch, g_attn);
    cudaGetSymbolAddress((void**)&prmax, g_rmax);
    cudaGetSymbolAddress((void**)&prinv, g_rinv);

    float* attn = ((long long)out_size >= BLD + BHLL) ? (out + BLD)
                                                      : pattn_scratch;

    dim3 blk(256);

    // 1) QKV projections
    {
        dim3 grd(Dq / 128, (Bq * Lq) / 128, 1);
        gemm_nt<<<grd, blk>>>(query, Wq, pq, Dq, Dq, Dq, Dq,
                              0, 0, 0, 0, 0, 0, 1, 1.0f, (const float*)0);
        gemm_nt<<<grd, blk>>>(key,   Wk, pk, Dq, Dq, Dq, Dq,
                              0, 0, 0, 0, 0, 0, 1, 1.0f, (const float*)0);
        gemm_nt<<<grd, blk>>>(value, Wv, pv, Dq, Dq, Dq, Dq,
                              0, 0, 0, 0, 0, 0, 1, 1.0f, (const float*)0);
    }

    // 2) Scores: per (b,h): S = (1/8) * Q_bh @ K_bh^T
    {
        dim3 grd(Lq / 128, Lq / 128, Bq * Hq);
        gemm_nt<<<grd, blk>>>(pq, pk, attn, HDq, Dq, Dq, Lq,
                              (long long)Lq * Dq, (long long)HDq,
                              (long long)Lq * Dq, (long long)HDq,
                              (long long)Hq * Lq * Lq, (long long)Lq * Lq,
                              Hq, 0.125f, (const float*)0);
    }

    // 3) Softmax stats (rowmax + 1/sumexp), one warp per row
    softmax_stats<<<(Bq * Hq * Lq) / 8, blk>>>(attn, prmax, prinv);

    // 4) Fused normalize + AV: writes normalized attention in place + out_head
    {
        dim3 grd(Lq / 128, 1, Bq * Hq);
        av_norm<<<grd, dim3(128)>>>(attn, pv, poh, prmax, prinv);
    }

    // 5) Output projection: out = out_head @ Wo^T + bo
    {
        dim3 grd(Dq / 128, (Bq * Lq) / 128, 1);
        gemm_nt<<<grd, blk>>>(poh, Wo, out, Dq, Dq, Dq, Dq,
                              0, 0, 0, 0, 0, 0, 1, 1.0f, bo);
    }
}

// round 16
// speedup vs baseline: 1.1137x; 1.0467x over previous
#include <cuda_runtime.h>
#include <math.h>

// Problem constants
#define Bq  4
#define Lq  2048
#define Dq  1024
#define Hq  16
#define HDq 64

typedef unsigned long long u64;

// Scratch (allocation-free rule: __device__ globals)
__device__ float g_q [(size_t)Bq * Lq * Dq];
__device__ float g_k [(size_t)Bq * Lq * Dq];
__device__ float g_v [(size_t)Bq * Lq * Dq];
__device__ float g_oh[(size_t)Bq * Lq * Dq];
__device__ float g_rmax[(size_t)Bq * Hq * Lq];
__device__ float g_rinv[(size_t)Bq * Hq * Lq];
__device__ float2 g_pstat[(size_t)Bq * Hq * Lq * 16];   // per (row, ntile) partial (max, sum)
// Fallback attention scratch in case d_out only holds `out`
__device__ float g_attn[(size_t)Bq * Hq * Lq * Lq];

// ---------------------------------------------------------------------------
// Packed f32x2 helpers
// ---------------------------------------------------------------------------
__device__ __forceinline__ void fma2(u64& d, u64 a, u64 b) {
    asm("fma.rn.f32x2 %0, %1, %2, %0;" : "+l"(d) : "l"(a), "l"(b));
}
__device__ __forceinline__ void mul2(u64& d, u64 a, u64 b) {
    asm("mul.rn.f32x2 %0, %1, %2;" : "=l"(d) : "l"(a), "l"(b));
}
__device__ __forceinline__ void add2(u64& d, u64 a, u64 b) {
    asm("add.rn.f32x2 %0, %1, %2;" : "=l"(d) : "l"(a), "l"(b));
}
__device__ __forceinline__ u64 dup2(float x) {
    u64 r;
    asm("mov.b64 %0, {%1, %1};" : "=l"(r) : "f"(x));
    return r;
}
__device__ __forceinline__ void unpack2(u64 v, float& lo, float& hi) {
    asm("mov.b64 {%0, %1}, %2;" : "=f"(lo), "=f"(hi) : "l"(v));
}

// ---------------------------------------------------------------------------
// NT GEMM (R12-proven): C[m,n] = alpha * sum_k A[m,k]*B[n,k] (+bias[n])
// 128x128 tile, BK=8, 256 threads, 8x8 outputs as packed f32x2 accumulators.
// Double-buffered smem + register prefetch. Used for QKV + output projection.
// ---------------------------------------------------------------------------
__global__ __launch_bounds__(256)
void gemm_nt(const float* __restrict__ A, const float* __restrict__ B,
             float* __restrict__ C,
             int K, int lda, int ldb, int ldc,
             float alpha, const float* __restrict__ bias)
{
    const int bm = blockIdx.y * 128;
    const int bn = blockIdx.x * 128;

    __shared__ float As[2][8][128];
    __shared__ float Bs[2][8][128];

    const int tid = threadIdx.x;
    const int tx  = tid & 15;
    const int ty  = tid >> 4;
    const int lr  = tid >> 1;
    const int lk  = (tid & 1) << 2;

    const float* Ap = A + (long long)(bm + lr) * lda + lk;
    const float* Bp = B + (long long)(bn + lr) * ldb + lk;

    u64 acc[8][4];
#pragma unroll
    for (int i = 0; i < 8; i++)
#pragma unroll
        for (int j = 0; j < 4; j++) acc[i][j] = 0ull;

    float4 a4 = *(const float4*)(Ap);
    float4 b4 = *(const float4*)(Bp);
    As[0][lk + 0][lr] = a4.x; As[0][lk + 1][lr] = a4.y;
    As[0][lk + 2][lr] = a4.z; As[0][lk + 3][lr] = a4.w;
    Bs[0][lk + 0][lr] = b4.x; Bs[0][lk + 1][lr] = b4.y;
    Bs[0][lk + 2][lr] = b4.z; Bs[0][lk + 3][lr] = b4.w;
    __syncthreads();

    int p = 0;
    for (int k0 = 0; k0 < K; k0 += 8) {
        const bool nxt = (k0 + 8) < K;
        if (nxt) {
            a4 = *(const float4*)(Ap + k0 + 8);
            b4 = *(const float4*)(Bp + k0 + 8);
        }
#pragma unroll
        for (int kk = 0; kk < 8; kk++) {
            float ar[8];
            *(float4*)(ar)     = *(const float4*)(&As[p][kk][ty * 4]);
            *(float4*)(ar + 4) = *(const float4*)(&As[p][kk][ty * 4 + 64]);
            ulonglong2 bl0 = *(const ulonglong2*)(&Bs[p][kk][tx * 4]);
            ulonglong2 bl1 = *(const ulonglong2*)(&Bs[p][kk][tx * 4 + 64]);
            u64 bb[4] = { bl0.x, bl0.y, bl1.x, bl1.y };
#pragma unroll
            for (int i = 0; i < 8; i++) {
                u64 ad = dup2(ar[i]);
#pragma unroll
                for (int j = 0; j < 4; j++) fma2(acc[i][j], ad, bb[j]);
            }
        }
        if (nxt) {
            p ^= 1;
            As[p][lk + 0][lr] = a4.x; As[p][lk + 1][lr] = a4.y;
            As[p][lk + 2][lr] = a4.z; As[p][lk + 3][lr] = a4.w;
            Bs[p][lk + 0][lr] = b4.x; Bs[p][lk + 1][lr] = b4.y;
            Bs[p][lk + 2][lr] = b4.z; Bs[p][lk + 3][lr] = b4.w;
            __syncthreads();
        }
    }

    u64 alpha2 = dup2(alpha);
#pragma unroll
    for (int ih = 0; ih < 2; ih++) {
#pragma unroll
        for (int i = 0; i < 4; i++) {
            int r = bm + ty * 4 + i + ih * 64;
#pragma unroll
            for (int jh = 0; jh < 2; jh++) {
                int c = bn + tx * 4 + jh * 64;
                u64 v0 = acc[ih * 4 + i][jh * 2 + 0];
                u64 v1 = acc[ih * 4 + i][jh * 2 + 1];
                mul2(v0, v0, alpha2);
                mul2(v1, v1, alpha2);
                if (bias) {
                    ulonglong2 bb = *(const ulonglong2*)(&bias[c]);
                    add2(v0, v0, bb.x);
                    add2(v1, v1, bb.y);
                }
                ulonglong2 ov; ov.x = v0; ov.y = v1;
                *(ulonglong2*)(C + (long long)r * ldc + c) = ov;
            }
        }
    }
}

// ---------------------------------------------------------------------------
// Scores + partial softmax stats. Specialized K=64 NT GEMM per (b,h):
// E = 0.125 * Q_bh @ K_bh^T. Whole 128x64 A/B tiles loaded once (one sync).
// Epilogue computes per-(row, 128-col tile) partial (max, sumexp) via
// half-warp shuffles; exp guarded by (c >= m - 87) so it almost never fires.
// Dynamic smem: 64KB (As 32KB + Bs 32KB).
// ---------------------------------------------------------------------------
__global__ __launch_bounds__(256)
void scores_stats(const float* __restrict__ Q, const float* __restrict__ K,
                  float* __restrict__ E, float2* __restrict__ pstat)
{
    extern __shared__ float sm[];
    float (*As)[128] = (float(*)[128])sm;            // [64][128]
    float (*Bs)[128] = (float(*)[128])(sm + 64*128); // [64][128]

    const int z  = blockIdx.z;
    const int bq = z >> 4, hq = z & 15;
    const int bm = blockIdx.y * 128;
    const int bn = blockIdx.x * 128;

    const float* Ab = Q + ((long long)bq * Lq) * Dq + hq * HDq;
    const float* Bb = K + ((long long)bq * Lq) * Dq + hq * HDq;
    float*       Eb = E + (long long)z * Lq * Lq;

    const int tid = threadIdx.x;
    const int tx  = tid & 15;
    const int ty  = tid >> 4;
    const int lr  = tid >> 1;
    const int lk  = (tid & 1) << 2;

    const float* Ap = Ab + (long long)(bm + lr) * Dq + lk;
    const float* Bp = Bb + (long long)(bn + lr) * Dq + lk;

    // Load full K=64 tiles (8 float4 per thread per matrix), then one sync.
#pragma unroll
    for (int j = 0; j < 8; j++) {
        float4 a4 = *(const float4*)(Ap + 8 * j);
        float4 b4 = *(const float4*)(Bp + 8 * j);
        int kb = lk + 8 * j;
        As[kb + 0][lr] = a4.x; As[kb + 1][lr] = a4.y;
        As[kb + 2][lr] = a4.z; As[kb + 3][lr] = a4.w;
        Bs[kb + 0][lr] = b4.x; Bs[kb + 1][lr] = b4.y;
        Bs[kb + 2][lr] = b4.z; Bs[kb + 3][lr] = b4.w;
    }

    u64 acc[8][4];
#pragma unroll
    for (int i = 0; i < 8; i++)
#pragma unroll
        for (int j = 0; j < 4; j++) acc[i][j] = 0ull;

    __syncthreads();

#pragma unroll 16
    for (int kk = 0; kk < 64; kk++) {
        float ar[8];
        *(float4*)(ar)     = *(const float4*)(&As[kk][ty * 4]);
        *(float4*)(ar + 4) = *(const float4*)(&As[kk][ty * 4 + 64]);
        ulonglong2 bl0 = *(const ulonglong2*)(&Bs[kk][tx * 4]);
        ulonglong2 bl1 = *(const ulonglong2*)(&Bs[kk][tx * 4 + 64]);
        u64 bb[4] = { bl0.x, bl0.y, bl1.x, bl1.y };
#pragma unroll
        for (int i = 0; i < 8; i++) {
            u64 ad = dup2(ar[i]);
#pragma unroll
            for (int j = 0; j < 4; j++) fma2(acc[i][j], ad, bb[j]);
        }
    }

    // Epilogue: scale, store E, partial stats.
    const u64 alpha2 = dup2(0.125f);
#pragma unroll
    for (int ih = 0; ih < 2; ih++) {
#pragma unroll
        for (int i = 0; i < 4; i++) {
            const int r = ty * 4 + i + ih * 64;   // local row 0..127
            u64 v0 = acc[ih * 4 + i][0];
            u64 v1 = acc[ih * 4 + i][1];
            u64 v2 = acc[ih * 4 + i][2];
            u64 v3 = acc[ih * 4 + i][3];
            mul2(v0, v0, alpha2); mul2(v1, v1, alpha2);
            mul2(v2, v2, alpha2); mul2(v3, v3, alpha2);
            float c[8];
            unpack2(v0, c[0], c[1]); unpack2(v1, c[2], c[3]);
            unpack2(v2, c[4], c[5]); unpack2(v3, c[6], c[7]);

            float* erow = Eb + (long long)(bm + r) * Lq + bn;
            *(float4*)(erow + tx * 4)      = make_float4(c[0], c[1], c[2], c[3]);
            *(float4*)(erow + tx * 4 + 64) = make_float4(c[4], c[5], c[6], c[7]);

            // per-thread max over 8 cols, reduce across the 16-lane tx group
            float m = c[0];
#pragma unroll
            for (int j = 1; j < 8; j++) m = fmaxf(m, c[j]);
#pragma unroll
            for (int o = 8; o; o >>= 1)
                m = fmaxf(m, __shfl_xor_sync(0xffffffffu, m, o));

            float s = 0.f;
#pragma unroll
            for (int j = 0; j < 8; j++)
                if (c[j] >= m - 87.0f) s += expf(c[j] - m);
#pragma unroll
            for (int o = 8; o; o >>= 1)
                s += __shfl_xor_sync(0xffffffffu, s, o);

            if (tx == 0) {
                pstat[((long long)z * Lq + bm + r) * 16 + blockIdx.x] =
                    make_float2(m, s);
            }
        }
    }
}

// ---------------------------------------------------------------------------
// Fold 16 per-tile partials into rowmax + 1/sum. One thread per row.
// ---------------------------------------------------------------------------
__global__ __launch_bounds__(256)
void reduce_stats(const float2* __restrict__ pstat,
                  float* __restrict__ rmax, float* __restrict__ rinv)
{
    const long long row = (long long)blockIdx.x * 256 + threadIdx.x;
    const float2* p = pstat + row * 16;

    float2 v[16];
#pragma unroll
    for (int i = 0; i < 16; i++) v[i] = p[i];

    float M = v[0].x;
#pragma unroll
    for (int i = 1; i < 16; i++) M = fmaxf(M, v[i].x);

    float S = 0.f;
#pragma unroll
    for (int i = 0; i < 16; i++) S += v[i].y * expf(v[i].x - M);

    rmax[row] = M;
    rinv[row] = 1.0f / S;
}

// ---------------------------------------------------------------------------
// Fused normalize + AV (R15): per (b,h), 128-row tile, 128 threads.
// p = expf(e - rowmax) * rowinv written back in place AND staged for the
// AV micro-GEMM. O[128x64] = P[128x2048] @ V[2048x64].
// ---------------------------------------------------------------------------
__global__ __launch_bounds__(128)
void av_norm(float* __restrict__ E,
             const float* __restrict__ V,
             float* __restrict__ C,
             const float* __restrict__ rmax,
             const float* __restrict__ rinv)
{
    int z  = blockIdx.z;
    int bq = z / Hq, hq = z % Hq;
    float*       Ab = E + (long long)z * Lq * Lq;
    const float* Bb = V + (long long)bq * Lq * Dq + hq * HDq;
    float*       Cb = C + (long long)bq * Lq * Dq + hq * HDq;

    const int bm = blockIdx.x * 128;

    __shared__ float As[2][8][128];
    __shared__ float Bs[2][8][64];

    const int tid = threadIdx.x;
    const int tx  = tid & 7;
    const int ty  = tid >> 3;

    float* Ap = Ab + (long long)(bm + tid) * Lq;
    const int bvr = tid >> 4;
    const int bvc = (tid & 15) * 4;
    const float* Bp = Bb + (long long)bvr * Dq + bvc;

    const float em  = rmax[(long long)z * Lq + bm + tid];
    const float inv = rinv[(long long)z * Lq + bm + tid];

    u64 acc[8][4];
#pragma unroll
    for (int i = 0; i < 8; i++)
#pragma unroll
        for (int j = 0; j < 4; j++) acc[i][j] = 0ull;

    float4 a0 = *(const float4*)(Ap);
    float4 a1 = *(const float4*)(Ap + 4);
    float4 b0 = *(const float4*)(Bp);
    a0.x = expf(a0.x - em) * inv; a0.y = expf(a0.y - em) * inv;
    a0.z = expf(a0.z - em) * inv; a0.w = expf(a0.w - em) * inv;
    a1.x = expf(a1.x - em) * inv; a1.y = expf(a1.y - em) * inv;
    a1.z = expf(a1.z - em) * inv; a1.w = expf(a1.w - em) * inv;
    As[0][0][tid] = a0.x; As[0][1][tid] = a0.y;
    As[0][2][tid] = a0.z; As[0][3][tid] = a0.w;
    As[0][4][tid] = a1.x; As[0][5][tid] = a1.y;
    As[0][6][tid] = a1.z; As[0][7][tid] = a1.w;
    *(float4*)(Ap)     = a0;
    *(float4*)(Ap + 4) = a1;
    *(float4*)(&Bs[0][bvr][bvc]) = b0;
    __syncthreads();

    int p = 0;
    for (int k0 = 0; k0 < Lq; k0 += 8) {
        const bool nxt = (k0 + 8) < Lq;
        if (nxt) {
            a0 = *(const float4*)(Ap + k0 + 8);
            a1 = *(const float4*)(Ap + k0 + 12);
            b0 = *(const float4*)(Bp + (long long)(k0 + 8) * Dq);
        }
#pragma unroll
        for (int kk = 0; kk < 8; kk++) {
            float ar[8];
            *(float4*)(ar)     = *(const float4*)(&As[p][kk][ty * 4]);
            *(float4*)(ar + 4) = *(const float4*)(&As[p][kk][ty * 4 + 64]);
            ulonglong2 bl0 = *(const ulonglong2*)(&Bs[p][kk][tx * 4]);
            ulonglong2 bl1 = *(const ulonglong2*)(&Bs[p][kk][tx * 4 + 32]);
            u64 bb[4] = { bl0.x, bl0.y, bl1.x, bl1.y };
#pragma unroll
            for (int i = 0; i < 8; i++) {
                u64 ad = dup2(ar[i]);
#pragma unroll
                for (int j = 0; j < 4; j++) fma2(acc[i][j], ad, bb[j]);
            }
        }
        if (nxt) {
            a0.x = expf(a0.x - em) * inv; a0.y = expf(a0.y - em) * inv;
            a0.z = expf(a0.z - em) * inv; a0.w = expf(a0.w - em) * inv;
            a1.x = expf(a1.x - em) * inv; a1.y = expf(a1.y - em) * inv;
            a1.z = expf(a1.z - em) * inv; a1.w = expf(a1.w - em) * inv;
            p ^= 1;
            As[p][0][tid] = a0.x; As[p][1][tid] = a0.y;
            As[p][2][tid] = a0.z; As[p][3][tid] = a0.w;
            As[p][4][tid] = a1.x; As[p][5][tid] = a1.y;
            As[p][6][tid] = a1.z; As[p][7][tid] = a1.w;
            *(float4*)(Ap + k0 + 8)  = a0;
            *(float4*)(Ap + k0 + 12) = a1;
            *(float4*)(&Bs[p][bvr][bvc]) = b0;
            __syncthreads();
        }
    }

#pragma unroll
    for (int ih = 0; ih < 2; ih++) {
#pragma unroll
        for (int i = 0; i < 4; i++) {
            int r = bm + ih * 64 + ty * 4 + i;
            ulonglong2 ov0, ov1;
            ov0.x = acc[ih * 4 + i][0]; ov0.y = acc[ih * 4 + i][1];
            ov1.x = acc[ih * 4 + i][2]; ov1.y = acc[ih * 4 + i][3];
            *(ulonglong2*)(&Cb[(long long)r * Dq + tx * 4])      = ov0;
            *(ulonglong2*)(&Cb[(long long)r * Dq + 32 + tx * 4]) = ov1;
        }
    }
}

// ---------------------------------------------------------------------------
// Launch
// ---------------------------------------------------------------------------
extern "C" void kernel_launch(void* const* d_in, const int* in_sizes, int n_in,
                              void* d_out, int out_size)
{
    const float* query = (const float*)d_in[0];
    const float* key   = (const float*)d_in[1];
    const float* value = (const float*)d_in[2];
    const float* Wq    = (const float*)d_in[3];
    const float* Wk    = (const float*)d_in[4];
    const float* Wv    = (const float*)d_in[5];
    const float* Wo    = (const float*)d_in[6];
    const float* bo    = (const float*)d_in[7];

    float* out = (float*)d_out;

    const long long BLD  = (long long)Bq * Lq * Dq;
    const long long BHLL = (long long)Bq * Hq * Lq * Lq;

    float *pq, *pk, *pv, *poh, *pattn_scratch, *prmax, *prinv;
    float2* ppstat;
    cudaGetSymbolAddress((void**)&pq,  g_q);
    cudaGetSymbolAddress((void**)&pk,  g_k);
    cudaGetSymbolAddress((void**)&pv,  g_v);
    cudaGetSymbolAddress((void**)&poh, g_oh);
    cudaGetSymbolAddress((void**)&pattn_scratch, g_attn);
    cudaGetSymbolAddress((void**)&prmax, g_rmax);
    cudaGetSymbolAddress((void**)&prinv, g_rinv);
    cudaGetSymbolAddress((void**)&ppstat, g_pstat);

    float* attn = ((long long)out_size >= BLD + BHLL) ? (out + BLD)
                                                      : pattn_scratch;

    static bool attr_done = false;
    if (!attr_done) {
        cudaFuncSetAttribute(scores_stats,
                             cudaFuncAttributeMaxDynamicSharedMemorySize,
                             64 * 1024);
        attr_done = true;
    }

    dim3 blk(256);

    // 1) QKV projections
    {
        dim3 grd(Dq / 128, (Bq * Lq) / 128);
        gemm_nt<<<grd, blk>>>(query, Wq, pq, Dq, Dq, Dq, Dq, 1.0f, (const float*)0);
        gemm_nt<<<grd, blk>>>(key,   Wk, pk, Dq, Dq, Dq, Dq, 1.0f, (const float*)0);
        gemm_nt<<<grd, blk>>>(value, Wv, pv, Dq, Dq, Dq, Dq, 1.0f, (const float*)0);
    }

    // 2) Scores (K=64 specialized) + partial softmax stats
    {
        dim3 grd(Lq / 128, Lq / 128, Bq * Hq);
        scores_stats<<<grd, blk, 64 * 1024>>>(pq, pk, attn, ppstat);
    }

    // 3) Fold partials into rowmax + 1/sum
    reduce_stats<<<(Bq * Hq * Lq) / 256, blk>>>(ppstat, prmax, prinv);

    // 4) Fused normalize + AV: normalized attention in place + out_head
    {
        dim3 grd(Lq / 128, 1, Bq * Hq);
        av_norm<<<grd, dim3(128)>>>(attn, pv, poh, prmax, prinv);
    }

    // 5) Output projection: out = out_head @ Wo^T + bo
    {
        dim3 grd(Dq / 128, (Bq * Lq) / 128);
        gemm_nt<<<grd, blk>>>(poh, Wo, out, Dq, Dq, Dq, Dq, 1.0f, bo);
    }
}